// round 11
// baseline (speedup 1.0000x reference)
#include <cuda_runtime.h>

// Problem constants
static constexpr int BATCH = 128;
static constexpr int W = 512;
static constexpr int NBLK = 4096;              // 8x8 blocks per image
static constexpr int L3N = 3 * NBLK;           // 12288 level-3 details per batch
static constexpr int KMED_LO = (L3N / 2) - 1;  // 6143
static constexpr int KMED_HI = (L3N / 2);      // 6144
static constexpr int MED_THREADS = 256;
static constexpr int VPT = L3N / MED_THREADS;  // 48 values per thread
static constexpr int XB = 16;                  // x-blocks per batch in pass1

// Speculative threshold = upper clip bound (realized whenever sigma*2.5 >= 0.2).
#define SPEC_T 0.2f

// Scratch (no cudaMalloc allowed)
__device__ float g_l3abs[BATCH * L3N];      // SoA: [batch][3][4096]
__device__ float g_thr[BATCH];
__device__ float g_sigma[BATCH];
__device__ float g_specp[BATCH * XB];       // pass1 partial sums (no atomics)
__device__ float g_fix[BATCH];              // fixup per-batch loss (written only if needed)

// ---------------------------------------------------------------------------
__device__ __forceinline__ float quad_detail(float a, float b, float c, float d,
                                             float t, float& cA) {
    float cH = 0.5f * (a + b - c - d);
    float cV = 0.5f * (a - b + c - d);
    float cD = 0.5f * (a - b - c + d);
    cA = 0.5f * (a + b + c + d);
    return fminf(fabsf(cH), t) + fminf(fabsf(cV), t) + fminf(fabsf(cD), t);
}

// Per 8x8 block: full 3-level Haar; weighted min(|c|,t) loss with
// (t3, t2, t1) = (t, t/2, t/4). |c - soft_threshold(c,t)| == min(|c|,t).
// Optionally emits |level-3 details| to SoA planes (stride NBLK).
__device__ __forceinline__ float block_loss(const float* __restrict__ src,
                                            float t3, float* l3dst, int gb) {
    const float t2 = 0.5f * t3;
    const float t1 = 0.25f * t3;
    float s1 = 0.0f, s2 = 0.0f;
    float cA1[4][4];
#pragma unroll
    for (int i = 0; i < 4; i++) {
        float4 a0 = __ldcs((const float4*)(src + (2 * i) * W));
        float4 a1 = __ldcs((const float4*)(src + (2 * i) * W + 4));
        float4 b0 = __ldcs((const float4*)(src + (2 * i + 1) * W));
        float4 b1 = __ldcs((const float4*)(src + (2 * i + 1) * W + 4));
        s1 += quad_detail(a0.x, a0.y, b0.x, b0.y, t1, cA1[i][0]);
        s1 += quad_detail(a0.z, a0.w, b0.z, b0.w, t1, cA1[i][1]);
        s1 += quad_detail(a1.x, a1.y, b1.x, b1.y, t1, cA1[i][2]);
        s1 += quad_detail(a1.z, a1.w, b1.z, b1.w, t1, cA1[i][3]);
    }
    float cA2[2][2];
#pragma unroll
    for (int i = 0; i < 2; i++)
#pragma unroll
        for (int j = 0; j < 2; j++)
            s2 += quad_detail(cA1[2 * i][2 * j], cA1[2 * i][2 * j + 1],
                              cA1[2 * i + 1][2 * j], cA1[2 * i + 1][2 * j + 1],
                              t2, cA2[i][j]);

    float a = cA2[0][0], b = cA2[0][1], c = cA2[1][0], d = cA2[1][1];
    float cH3 = 0.5f * (a + b - c - d);
    float cV3 = 0.5f * (a - b + c - d);
    float cD3 = 0.5f * (a - b - c + d);
    float s3 = fminf(fabsf(cH3), t3) + fminf(fabsf(cV3), t3) + fminf(fabsf(cD3), t3);
    if (l3dst) {                       // coalesced SoA stores
        l3dst[gb] = fabsf(cH3);
        l3dst[gb + NBLK] = fabsf(cV3);
        l3dst[gb + 2 * NBLK] = fabsf(cD3);
    }
    // weights: level_idx l over detail level (4-l); mean over n_l; /3; /level_idx
    return s3 * (1.0f / (3.0f * 4096.0f))
         + s2 * (1.0f / (6.0f * 16384.0f))
         + s1 * (1.0f / (9.0f * 65536.0f));
}

__device__ __forceinline__ float block_reduce(float s) {
#pragma unroll
    for (int off = 16; off; off >>= 1) s += __shfl_xor_sync(0xFFFFFFFFu, s, off);
    __shared__ float warp_s[8];
    if ((threadIdx.x & 31) == 0) warp_s[threadIdx.x >> 5] = s;
    __syncthreads();
    float v = 0.0f;
    if (threadIdx.x < 8) {
        v = warp_s[threadIdx.x];
#pragma unroll
        for (int off = 4; off; off >>= 1) v += __shfl_xor_sync(0xFFu, v, off);
    }
    return v;   // valid in thread 0
}

// ---------------------------------------------------------------------------
// Pass 1: single streamed read of pred. Emits level-3 |details| (SoA) and the
// speculative loss partial at t = SPEC_T. No atomics, no pre-zeroing.
__global__ void k_pass1(const float* __restrict__ in) {
    const int batch = blockIdx.y;
    const int gb = blockIdx.x * blockDim.x + threadIdx.x;   // 0..4095
    const float* src = in + ((size_t)batch << 18)
                          + (size_t)((gb >> 6) << 3) * W + ((gb & 63) << 3);
    float s = block_loss(src, SPEC_T, g_l3abs + (size_t)batch * L3N, gb);
    float tot = block_reduce(s);
    if (threadIdx.x == 0) g_specp[batch * XB + blockIdx.x] = tot;
}

// ---------------------------------------------------------------------------
// Median (+ inline fixup): one block per batch. Exact k=6143 order statistic
// via 4-pass radix-8 select on nonneg float bit patterns; k=6144 from
// count(<=) + min(>). Warp-aggregated histogram atomics, shfl-based scan.
// If the true threshold differs from SPEC_T, this same block recomputes the
// batch loss from pred (cold path; never taken for in-range sigma).
__global__ void __launch_bounds__(MED_THREADS) k_median_fix(const float* __restrict__ in) {
    __shared__ unsigned s_hist[256];
    __shared__ unsigned s_wsum[8];
    __shared__ unsigned s_sel;
    __shared__ unsigned s_krem;
    __shared__ float s_thr;

    const int batch = blockIdx.x;
    const int tid = threadIdx.x;
    const int lane = tid & 31;
    const float* src = g_l3abs + (size_t)batch * L3N;

    unsigned v[VPT];
#pragma unroll
    for (int j = 0; j < VPT; j++)
        v[j] = __float_as_uint(src[tid + j * MED_THREADS]);

    if (tid == 0) s_krem = (unsigned)KMED_LO;
    unsigned prefix = 0;
#pragma unroll 1
    for (int shift = 24; shift >= 0; shift -= 8) {
        s_hist[tid] = 0;
        __syncthreads();
#pragma unroll
        for (int j = 0; j < VPT; j++) {
            unsigned u = v[j];
            bool match = (shift == 24) || ((u >> (shift + 8)) == prefix);
            unsigned bin = (u >> shift) & 0xFFu;
            unsigned key = match ? bin : 0xFFFFFFFFu;
            unsigned mm = __match_any_sync(0xFFFFFFFFu, key);
            if (match && lane == (__ffs(mm) - 1))
                atomicAdd(&s_hist[bin], (unsigned)__popc(mm));
        }
        __syncthreads();
        // inclusive scan of 256 bins: per-warp shfl scan + cross-warp offsets
        unsigned h = s_hist[tid];
        unsigned sc = h;
#pragma unroll
        for (int off = 1; off < 32; off <<= 1) {
            unsigned t = __shfl_up_sync(0xFFFFFFFFu, sc, off);
            if (lane >= off) sc += t;
        }
        if (lane == 31) s_wsum[tid >> 5] = sc;
        __syncthreads();
        if (tid < 8) {
            unsigned w = s_wsum[tid];
#pragma unroll
            for (int off = 1; off < 8; off <<= 1) {
                unsigned t = __shfl_up_sync(0xFFu, w, off);
                if (tid >= off) w += t;
            }
            s_wsum[tid] = w;
        }
        __syncthreads();
        unsigned incl = sc + ((tid >= 32) ? s_wsum[(tid >> 5) - 1] : 0u);
        unsigned excl = incl - h;
        unsigned kk = s_krem;
        if (kk >= excl && kk < incl) {   // unique winner (h > 0)
            s_sel = (unsigned)tid;
            s_krem = kk - excl;
        }
        __syncthreads();
        prefix = (prefix << 8) | s_sel;
        __syncthreads();
    }
    const unsigned medLO = prefix;

    // count(v <= medLO) and min over v > medLO
    unsigned cnt = 0, mn = 0x7F800000u;
#pragma unroll
    for (int j = 0; j < VPT; j++) {
        if (v[j] <= medLO) cnt++;
        else mn = min(mn, v[j]);
    }
#pragma unroll
    for (int off = 16; off; off >>= 1) {
        cnt += __shfl_xor_sync(0xFFFFFFFFu, cnt, off);
        mn = min(mn, __shfl_xor_sync(0xFFFFFFFFu, mn, off));
    }
    if (lane == 0) { s_hist[tid >> 5] = cnt; s_wsum[tid >> 5] = mn; }
    __syncthreads();
    if (tid == 0) {
        unsigned ctot = 0, mtot = 0x7F800000u;
#pragma unroll
        for (int w = 0; w < 8; w++) { ctot += s_hist[w]; mtot = min(mtot, s_wsum[w]); }
        unsigned medHI = (ctot > (unsigned)KMED_HI) ? medLO : mtot;
        float median = 0.5f * (__uint_as_float(medLO) + __uint_as_float(medHI));
        float sigma = median * 1.4825796886582653f;   // 1/0.6745
        float thr = fminf(fmaxf(sigma * 2.5f, 0.05f), SPEC_T);
        g_sigma[batch] = sigma;
        g_thr[batch] = thr;
        s_thr = thr;
    }
    __syncthreads();

    // Cold fixup path: recompute this batch's loss at the true threshold.
    const float thr = s_thr;
    if (thr != SPEC_T) {
        float s = 0.0f;
        const float* base = in + ((size_t)batch << 18);
#pragma unroll 1
        for (int it = 0; it < NBLK / MED_THREADS; it++) {
            int gb = tid + it * MED_THREADS;
            const float* p = base + (size_t)((gb >> 6) << 3) * W + ((gb & 63) << 3);
            s += block_loss(p, thr, nullptr, 0);
        }
        float tot = block_reduce(s);
        if (tid == 0) g_fix[batch] = tot;
    }
}

// ---------------------------------------------------------------------------
// Final: per batch pick spec-partials sum or fix, average; write outputs.
__global__ void k_final(float* __restrict__ out) {
    const int tid = threadIdx.x;   // 128 threads = one per batch
    float l;
    if (g_thr[tid] == SPEC_T) {
        l = 0.0f;
#pragma unroll
        for (int j = 0; j < XB; j++) l += g_specp[tid * XB + j];
    } else {
        l = g_fix[tid];
    }
    float sg = g_sigma[tid];
#pragma unroll
    for (int off = 16; off; off >>= 1) {
        l += __shfl_xor_sync(0xFFFFFFFFu, l, off);
        sg += __shfl_xor_sync(0xFFFFFFFFu, sg, off);
    }
    __shared__ float sl[4], ss[4];
    if ((tid & 31) == 0) { sl[tid >> 5] = l; ss[tid >> 5] = sg; }
    __syncthreads();
    if (tid == 0) {
        out[0] = (sl[0] + sl[1] + sl[2] + sl[3]) * (1.0f / (float)BATCH);
        out[1] = (ss[0] + ss[1] + ss[2] + ss[3]) * (1.0f / (float)BATCH);
    }
}

// ---------------------------------------------------------------------------
extern "C" void kernel_launch(void* const* d_in, const int* in_sizes, int n_in,
                              void* d_out, int out_size) {
    const float* pred = (const float*)d_in[0];
    float* out = (float*)d_out;

    k_pass1<<<dim3(XB, BATCH), 256>>>(pred);
    k_median_fix<<<BATCH, MED_THREADS>>>(pred);
    k_final<<<1, 128>>>(out);
}

// round 12
// speedup vs baseline: 1.1745x; 1.1745x over previous
#include <cuda_runtime.h>

// Problem constants
static constexpr int BATCH = 128;
static constexpr int W = 512;
static constexpr int NBLK = 4096;              // 8x8 blocks per image
static constexpr int L3N = 3 * NBLK;           // 12288 level-3 details per batch
static constexpr int KMED_LO = (L3N / 2) - 1;  // 6143
static constexpr int KMED_HI = (L3N / 2);      // 6144
static constexpr int MED_THREADS = 256;
static constexpr int VPT = L3N / MED_THREADS;  // 48 values per thread
static constexpr int XB = 16;                  // x-blocks per batch in pass1

// Speculative threshold = upper clip bound (realized whenever sigma*2.5 >= 0.2).
#define SPEC_T 0.2f

// Scratch (no cudaMalloc allowed)
__device__ float g_l3abs[BATCH * L3N];      // SoA: [batch][3][4096]
__device__ float g_thr[BATCH];
__device__ float g_sigma[BATCH];
__device__ float g_specp[BATCH * XB];       // pass1 partial sums (no atomics, no init)
__device__ float g_fix[BATCH];              // fixup loss (read only if written)

// ---------------------------------------------------------------------------
__device__ __forceinline__ float quad_detail(float a, float b, float c, float d,
                                             float t, float& cA) {
    float cH = 0.5f * (a + b - c - d);
    float cV = 0.5f * (a - b + c - d);
    float cD = 0.5f * (a - b - c + d);
    cA = 0.5f * (a + b + c + d);
    return fminf(fabsf(cH), t) + fminf(fabsf(cV), t) + fminf(fabsf(cD), t);
}

// Per 8x8 block: full 3-level Haar; weighted min(|c|,t) loss with
// (t3, t2, t1) = (t, t/2, t/4). |c - soft_threshold(c,t)| == min(|c|,t).
// Optionally emits |level-3 details| to SoA planes (stride NBLK).
__device__ __forceinline__ float block_loss(const float* __restrict__ src,
                                            float t3, float* l3dst, int gb) {
    const float t2 = 0.5f * t3;
    const float t1 = 0.25f * t3;
    float s1 = 0.0f, s2 = 0.0f;
    float cA1[4][4];
#pragma unroll
    for (int i = 0; i < 4; i++) {
        float4 a0 = __ldcs((const float4*)(src + (2 * i) * W));
        float4 a1 = __ldcs((const float4*)(src + (2 * i) * W + 4));
        float4 b0 = __ldcs((const float4*)(src + (2 * i + 1) * W));
        float4 b1 = __ldcs((const float4*)(src + (2 * i + 1) * W + 4));
        s1 += quad_detail(a0.x, a0.y, b0.x, b0.y, t1, cA1[i][0]);
        s1 += quad_detail(a0.z, a0.w, b0.z, b0.w, t1, cA1[i][1]);
        s1 += quad_detail(a1.x, a1.y, b1.x, b1.y, t1, cA1[i][2]);
        s1 += quad_detail(a1.z, a1.w, b1.z, b1.w, t1, cA1[i][3]);
    }
    float cA2[2][2];
#pragma unroll
    for (int i = 0; i < 2; i++)
#pragma unroll
        for (int j = 0; j < 2; j++)
            s2 += quad_detail(cA1[2 * i][2 * j], cA1[2 * i][2 * j + 1],
                              cA1[2 * i + 1][2 * j], cA1[2 * i + 1][2 * j + 1],
                              t2, cA2[i][j]);

    float a = cA2[0][0], b = cA2[0][1], c = cA2[1][0], d = cA2[1][1];
    float cH3 = 0.5f * (a + b - c - d);
    float cV3 = 0.5f * (a - b + c - d);
    float cD3 = 0.5f * (a - b - c + d);
    float s3 = fminf(fabsf(cH3), t3) + fminf(fabsf(cV3), t3) + fminf(fabsf(cD3), t3);
    if (l3dst) {                       // coalesced SoA stores
        l3dst[gb] = fabsf(cH3);
        l3dst[gb + NBLK] = fabsf(cV3);
        l3dst[gb + 2 * NBLK] = fabsf(cD3);
    }
    // weights: level_idx l over detail level (4-l); mean over n_l; /3; /level_idx
    return s3 * (1.0f / (3.0f * 4096.0f))
         + s2 * (1.0f / (6.0f * 16384.0f))
         + s1 * (1.0f / (9.0f * 65536.0f));
}

__device__ __forceinline__ float block_reduce(float s) {
#pragma unroll
    for (int off = 16; off; off >>= 1) s += __shfl_xor_sync(0xFFFFFFFFu, s, off);
    __shared__ float warp_s[8];
    if ((threadIdx.x & 31) == 0) warp_s[threadIdx.x >> 5] = s;
    __syncthreads();
    float v = 0.0f;
    if (threadIdx.x < 8) {
        v = warp_s[threadIdx.x];
#pragma unroll
        for (int off = 4; off; off >>= 1) v += __shfl_xor_sync(0xFFu, v, off);
    }
    return v;   // valid in thread 0
}

// ---------------------------------------------------------------------------
// Pass 1: single streamed read of pred. Emits level-3 |details| (SoA) and the
// speculative loss partial at t = SPEC_T. No atomics, no pre-zeroing.
__global__ void k_pass1(const float* __restrict__ in) {
    const int batch = blockIdx.y;
    const int gb = blockIdx.x * blockDim.x + threadIdx.x;   // 0..4095
    const float* src = in + ((size_t)batch << 18)
                          + (size_t)((gb >> 6) << 3) * W + ((gb & 63) << 3);
    float s = block_loss(src, SPEC_T, g_l3abs + (size_t)batch * L3N, gb);
    float tot = block_reduce(s);
    if (threadIdx.x == 0) g_specp[batch * XB + blockIdx.x] = tot;
}

// ---------------------------------------------------------------------------
// Median: one block per batch — R9's proven version, verbatim. Exact k=6143
// order statistic via 4-pass radix-8 select on nonneg float bit patterns
// (values in registers, plain smem atomics + Hillis-Steele 256-bin scan);
// k=6144 derived from count(<=) + min(>). Median is permutation-invariant,
// so the SoA scratch layout needs no index change.
__global__ void __launch_bounds__(MED_THREADS) k_median() {
    __shared__ unsigned s_hist[256];
    __shared__ unsigned s_scan[256];
    __shared__ unsigned s_sel;
    __shared__ unsigned s_krem;
    __shared__ unsigned s_red[8];

    const int batch = blockIdx.x;
    const int tid = threadIdx.x;
    const float* src = g_l3abs + (size_t)batch * L3N;

    unsigned v[VPT];
#pragma unroll
    for (int j = 0; j < VPT; j++)
        v[j] = __float_as_uint(src[tid + j * MED_THREADS]);

    if (tid == 0) s_krem = (unsigned)KMED_LO;
    unsigned prefix = 0;
#pragma unroll 1
    for (int shift = 24; shift >= 0; shift -= 8) {
        s_hist[tid] = 0;
        __syncthreads();
#pragma unroll
        for (int j = 0; j < VPT; j++) {
            unsigned u = v[j];
            bool match = (shift == 24) || ((u >> (shift + 8)) == prefix);
            if (match) atomicAdd(&s_hist[(u >> shift) & 0xFFu], 1u);
        }
        __syncthreads();
        // Hillis-Steele inclusive scan over 256 bins
        unsigned h = s_hist[tid];
        s_scan[tid] = h;
        __syncthreads();
#pragma unroll
        for (int off = 1; off < 256; off <<= 1) {
            unsigned t = (tid >= off) ? s_scan[tid - off] : 0u;
            __syncthreads();
            s_scan[tid] += t;
            __syncthreads();
        }
        unsigned excl = s_scan[tid] - h;
        unsigned kk = s_krem;
        if (kk >= excl && kk < excl + h) {   // unique winner (h > 0)
            s_sel = (unsigned)tid;
            s_krem = kk - excl;
        }
        __syncthreads();
        prefix = (prefix << 8) | s_sel;
        __syncthreads();
    }
    const unsigned medLO = prefix;

    // count(v <= medLO) and min over v > medLO, reduced across the block
    unsigned cnt = 0, mn = 0x7F800000u;
#pragma unroll
    for (int j = 0; j < VPT; j++) {
        if (v[j] <= medLO) cnt++;
        else mn = min(mn, v[j]);
    }
#pragma unroll
    for (int off = 16; off; off >>= 1) {
        cnt += __shfl_xor_sync(0xFFFFFFFFu, cnt, off);
        mn = min(mn, __shfl_xor_sync(0xFFFFFFFFu, mn, off));
    }
    if ((tid & 31) == 0) { s_hist[tid >> 5] = cnt; s_red[tid >> 5] = mn; }
    __syncthreads();
    if (tid == 0) {
        unsigned ctot = 0, mtot = 0x7F800000u;
#pragma unroll
        for (int w = 0; w < 8; w++) { ctot += s_hist[w]; mtot = min(mtot, s_red[w]); }
        unsigned medHI = (ctot > (unsigned)KMED_HI) ? medLO : mtot;
        float median = 0.5f * (__uint_as_float(medLO) + __uint_as_float(medHI));
        float sigma = median * 1.4825796886582653f;   // 1/0.6745
        g_sigma[batch] = sigma;
        g_thr[batch] = fminf(fmaxf(sigma * 2.5f, 0.05f), SPEC_T);
    }
}

// ---------------------------------------------------------------------------
// Fixup: one block per batch (128 blocks, not 2048 — kills the 5.3us launch
// wave). Early-exits unless the true threshold differs from SPEC_T (never,
// for in-range sigma). Cold path loops the 16 chunks internally.
__global__ void k_fix(const float* __restrict__ in) {
    const int batch = blockIdx.x;
    const float thr = g_thr[batch];
    if (thr == SPEC_T) return;   // uniform across block
    float s = 0.0f;
    const float* base = in + ((size_t)batch << 18);
#pragma unroll 1
    for (int it = 0; it < NBLK / MED_THREADS; it++) {
        int gb = threadIdx.x + it * MED_THREADS;
        const float* p = base + (size_t)((gb >> 6) << 3) * W + ((gb & 63) << 3);
        s += block_loss(p, thr, nullptr, 0);
    }
    float tot = block_reduce(s);
    if (threadIdx.x == 0) g_fix[batch] = tot;
}

// ---------------------------------------------------------------------------
// Final: per batch pick spec-partials sum or fix, average; write outputs.
__global__ void k_final(float* __restrict__ out) {
    const int tid = threadIdx.x;   // 128 threads = one per batch
    float l;
    if (g_thr[tid] == SPEC_T) {
        l = 0.0f;
#pragma unroll
        for (int j = 0; j < XB; j++) l += g_specp[tid * XB + j];
    } else {
        l = g_fix[tid];
    }
    float sg = g_sigma[tid];
#pragma unroll
    for (int off = 16; off; off >>= 1) {
        l += __shfl_xor_sync(0xFFFFFFFFu, l, off);
        sg += __shfl_xor_sync(0xFFFFFFFFu, sg, off);
    }
    __shared__ float sl[4], ss[4];
    if ((tid & 31) == 0) { sl[tid >> 5] = l; ss[tid >> 5] = sg; }
    __syncthreads();
    if (tid == 0) {
        out[0] = (sl[0] + sl[1] + sl[2] + sl[3]) * (1.0f / (float)BATCH);
        out[1] = (ss[0] + ss[1] + ss[2] + ss[3]) * (1.0f / (float)BATCH);
    }
}

// ---------------------------------------------------------------------------
extern "C" void kernel_launch(void* const* d_in, const int* in_sizes, int n_in,
                              void* d_out, int out_size) {
    const float* pred = (const float*)d_in[0];
    float* out = (float*)d_out;

    k_pass1<<<dim3(XB, BATCH), 256>>>(pred);
    k_median<<<BATCH, MED_THREADS>>>();
    k_fix<<<BATCH, MED_THREADS>>>(pred);
    k_final<<<1, 128>>>(out);
}

// round 17
// speedup vs baseline: 1.3153x; 1.1199x over previous
#include <cuda_runtime.h>

// Problem constants
static constexpr int BATCH = 128;
static constexpr int W = 512;
static constexpr int NBLK = 4096;              // 8x8 blocks per image
static constexpr int L3N = 3 * NBLK;           // 12288 level-3 details per batch
static constexpr int KMED_LO = (L3N / 2) - 1;  // 6143
static constexpr int KMED_HI = (L3N / 2);      // 6144
static constexpr int MED_THREADS = 256;
static constexpr int VPT = L3N / MED_THREADS;  // 48 values per thread
static constexpr int XB = 16;                  // x-blocks per batch in pass1

// Speculative threshold = upper clip bound (realized whenever sigma*2.5 >= 0.2).
#define SPEC_T 0.2f

// Scratch (no cudaMalloc allowed)
__device__ float g_l3abs[BATCH * L3N];      // SoA: [batch][3][4096]
__device__ float g_specp[BATCH * XB];       // pass1 partial sums (no atomics, no init)
__device__ float g_loss[BATCH];             // per-batch final loss
__device__ float g_sigma[BATCH];
__device__ unsigned g_arrive;               // zero-init; reset by last block each call

// ---------------------------------------------------------------------------
__device__ __forceinline__ float quad_detail(float a, float b, float c, float d,
                                             float t, float& cA) {
    float cH = 0.5f * (a + b - c - d);
    float cV = 0.5f * (a - b + c - d);
    float cD = 0.5f * (a - b - c + d);
    cA = 0.5f * (a + b + c + d);
    return fminf(fabsf(cH), t) + fminf(fabsf(cV), t) + fminf(fabsf(cD), t);
}

// Per 8x8 block: full 3-level Haar; weighted min(|c|,t) loss with
// (t3, t2, t1) = (t, t/2, t/4). |c - soft_threshold(c,t)| == min(|c|,t).
// Optionally emits |level-3 details| to SoA planes (stride NBLK).
__device__ __forceinline__ float block_loss(const float* __restrict__ src,
                                            float t3, float* l3dst, int gb) {
    const float t2 = 0.5f * t3;
    const float t1 = 0.25f * t3;
    float s1 = 0.0f, s2 = 0.0f;
    float cA1[4][4];
#pragma unroll
    for (int i = 0; i < 4; i++) {
        float4 a0 = __ldcs((const float4*)(src + (2 * i) * W));
        float4 a1 = __ldcs((const float4*)(src + (2 * i) * W + 4));
        float4 b0 = __ldcs((const float4*)(src + (2 * i + 1) * W));
        float4 b1 = __ldcs((const float4*)(src + (2 * i + 1) * W + 4));
        s1 += quad_detail(a0.x, a0.y, b0.x, b0.y, t1, cA1[i][0]);
        s1 += quad_detail(a0.z, a0.w, b0.z, b0.w, t1, cA1[i][1]);
        s1 += quad_detail(a1.x, a1.y, b1.x, b1.y, t1, cA1[i][2]);
        s1 += quad_detail(a1.z, a1.w, b1.z, b1.w, t1, cA1[i][3]);
    }
    float cA2[2][2];
#pragma unroll
    for (int i = 0; i < 2; i++)
#pragma unroll
        for (int j = 0; j < 2; j++)
            s2 += quad_detail(cA1[2 * i][2 * j], cA1[2 * i][2 * j + 1],
                              cA1[2 * i + 1][2 * j], cA1[2 * i + 1][2 * j + 1],
                              t2, cA2[i][j]);

    float a = cA2[0][0], b = cA2[0][1], c = cA2[1][0], d = cA2[1][1];
    float cH3 = 0.5f * (a + b - c - d);
    float cV3 = 0.5f * (a - b + c - d);
    float cD3 = 0.5f * (a - b - c + d);
    float s3 = fminf(fabsf(cH3), t3) + fminf(fabsf(cV3), t3) + fminf(fabsf(cD3), t3);
    if (l3dst) {                       // coalesced SoA stores
        l3dst[gb] = fabsf(cH3);
        l3dst[gb + NBLK] = fabsf(cV3);
        l3dst[gb + 2 * NBLK] = fabsf(cD3);
    }
    // weights: level_idx l over detail level (4-l); mean over n_l; /3; /level_idx
    return s3 * (1.0f / (3.0f * 4096.0f))
         + s2 * (1.0f / (6.0f * 16384.0f))
         + s1 * (1.0f / (9.0f * 65536.0f));
}

__device__ __forceinline__ float block_reduce(float s) {
#pragma unroll
    for (int off = 16; off; off >>= 1) s += __shfl_xor_sync(0xFFFFFFFFu, s, off);
    __shared__ float warp_s[8];
    if ((threadIdx.x & 31) == 0) warp_s[threadIdx.x >> 5] = s;
    __syncthreads();
    float v = 0.0f;
    if (threadIdx.x < 8) {
        v = warp_s[threadIdx.x];
#pragma unroll
        for (int off = 4; off; off >>= 1) v += __shfl_xor_sync(0xFFu, v, off);
    }
    return v;   // valid in thread 0
}

// ---------------------------------------------------------------------------
// Pass 1: single streamed read of pred. Emits level-3 |details| (SoA) and the
// speculative loss partial at t = SPEC_T. No atomics, no pre-zeroing.
__global__ void k_pass1(const float* __restrict__ in) {
    const int batch = blockIdx.y;
    const int gb = blockIdx.x * blockDim.x + threadIdx.x;   // 0..4095
    const float* src = in + ((size_t)batch << 18)
                          + (size_t)((gb >> 6) << 3) * W + ((gb & 63) << 3);
    float s = block_loss(src, SPEC_T, g_l3abs + (size_t)batch * L3N, gb);
    float tot = block_reduce(s);
    if (threadIdx.x == 0) g_specp[batch * XB + blockIdx.x] = tot;
}

// ---------------------------------------------------------------------------
// Tail kernel: one block per batch. (1) exact median via R9-proven 4-pass
// radix-8 select; (2) cold fixup if thr != SPEC_T (re-reads this batch from
// pred); (3) per-batch loss written; (4) last arriving block reduces all 128
// batches and writes the two outputs. Arrival counter self-resets so graph
// replays stay deterministic.
__global__ void __launch_bounds__(MED_THREADS) k_tail(const float* __restrict__ in,
                                                      float* __restrict__ out) {
    __shared__ unsigned s_hist[256];
    __shared__ unsigned s_scan[256];
    __shared__ unsigned s_sel;
    __shared__ unsigned s_krem;
    __shared__ unsigned s_red[8];
    __shared__ float s_thr;
    __shared__ unsigned s_last;

    const int batch = blockIdx.x;
    const int tid = threadIdx.x;
    const float* src = g_l3abs + (size_t)batch * L3N;

    // ---- median (R9-proven) ----
    unsigned v[VPT];
#pragma unroll
    for (int j = 0; j < VPT; j++)
        v[j] = __float_as_uint(src[tid + j * MED_THREADS]);

    if (tid == 0) s_krem = (unsigned)KMED_LO;
    unsigned prefix = 0;
#pragma unroll 1
    for (int shift = 24; shift >= 0; shift -= 8) {
        s_hist[tid] = 0;
        __syncthreads();
#pragma unroll
        for (int j = 0; j < VPT; j++) {
            unsigned u = v[j];
            bool match = (shift == 24) || ((u >> (shift + 8)) == prefix);
            if (match) atomicAdd(&s_hist[(u >> shift) & 0xFFu], 1u);
        }
        __syncthreads();
        // Hillis-Steele inclusive scan over 256 bins
        unsigned h = s_hist[tid];
        s_scan[tid] = h;
        __syncthreads();
#pragma unroll
        for (int off = 1; off < 256; off <<= 1) {
            unsigned t = (tid >= off) ? s_scan[tid - off] : 0u;
            __syncthreads();
            s_scan[tid] += t;
            __syncthreads();
        }
        unsigned excl = s_scan[tid] - h;
        unsigned kk = s_krem;
        if (kk >= excl && kk < excl + h) {   // unique winner (h > 0)
            s_sel = (unsigned)tid;
            s_krem = kk - excl;
        }
        __syncthreads();
        prefix = (prefix << 8) | s_sel;
        __syncthreads();
    }
    const unsigned medLO = prefix;

    // count(v <= medLO) and min over v > medLO, reduced across the block
    unsigned cnt = 0, mn = 0x7F800000u;
#pragma unroll
    for (int j = 0; j < VPT; j++) {
        if (v[j] <= medLO) cnt++;
        else mn = min(mn, v[j]);
    }
#pragma unroll
    for (int off = 16; off; off >>= 1) {
        cnt += __shfl_xor_sync(0xFFFFFFFFu, cnt, off);
        mn = min(mn, __shfl_xor_sync(0xFFFFFFFFu, mn, off));
    }
    if ((tid & 31) == 0) { s_hist[tid >> 5] = cnt; s_red[tid >> 5] = mn; }
    __syncthreads();
    if (tid == 0) {
        unsigned ctot = 0, mtot = 0x7F800000u;
#pragma unroll
        for (int w = 0; w < 8; w++) { ctot += s_hist[w]; mtot = min(mtot, s_red[w]); }
        unsigned medHI = (ctot > (unsigned)KMED_HI) ? medLO : mtot;
        float median = 0.5f * (__uint_as_float(medLO) + __uint_as_float(medHI));
        float sigma = median * 1.4825796886582653f;   // 1/0.6745
        g_sigma[batch] = sigma;
        s_thr = fminf(fmaxf(sigma * 2.5f, 0.05f), SPEC_T);
    }
    __syncthreads();
    const float thr = s_thr;

    // ---- per-batch loss: spec partials (hot) or full recompute (cold) ----
    float loss_b;
    if (thr == SPEC_T) {
        float p = (tid < XB) ? g_specp[batch * XB + tid] : 0.0f;
#pragma unroll
        for (int off = 8; off; off >>= 1) p += __shfl_xor_sync(0xFFFFFFFFu, p, off);
        loss_b = p;   // valid in tid 0
    } else {
        float s = 0.0f;
        const float* base = in + ((size_t)batch << 18);
#pragma unroll 1
        for (int it = 0; it < NBLK / MED_THREADS; it++) {
            int gb = tid + it * MED_THREADS;
            const float* p = base + (size_t)((gb >> 6) << 3) * W + ((gb & 63) << 3);
            s += block_loss(p, thr, nullptr, 0);
        }
        loss_b = block_reduce(s);
    }

    // ---- last-block-done final reduction ----
    if (tid == 0) {
        g_loss[batch] = loss_b;
        __threadfence();
        unsigned old = atomicAdd(&g_arrive, 1u);
        s_last = (old == (unsigned)(BATCH - 1)) ? 1u : 0u;
    }
    __syncthreads();
    if (s_last) {
        __threadfence();
        float l = (tid < BATCH) ? g_loss[tid] : 0.0f;
        float sg = (tid < BATCH) ? g_sigma[tid] : 0.0f;
#pragma unroll
        for (int off = 16; off; off >>= 1) {
            l += __shfl_xor_sync(0xFFFFFFFFu, l, off);
            sg += __shfl_xor_sync(0xFFFFFFFFu, sg, off);
        }
        __shared__ float sl[8], ss[8];
        if ((tid & 31) == 0) { sl[tid >> 5] = l; ss[tid >> 5] = sg; }
        __syncthreads();
        if (tid == 0) {
            float L = 0.0f, S = 0.0f;
#pragma unroll
            for (int w = 0; w < 8; w++) { L += sl[w]; S += ss[w]; }
            out[0] = L * (1.0f / (float)BATCH);
            out[1] = S * (1.0f / (float)BATCH);
            g_arrive = 0;   // self-reset: deterministic across graph replays
        }
    }
}

// ---------------------------------------------------------------------------
extern "C" void kernel_launch(void* const* d_in, const int* in_sizes, int n_in,
                              void* d_out, int out_size) {
    const float* pred = (const float*)d_in[0];
    float* out = (float*)d_out;

    k_pass1<<<dim3(XB, BATCH), 256>>>(pred);
    k_tail<<<BATCH, MED_THREADS>>>(pred, out);
}